// round 1
// baseline (speedup 1.0000x reference)
#include <cuda_runtime.h>
#include <cuda_bf16.h>
#include <cstdint>

// Problem constants
#define B_   256
#define CIN  64
#define COUT 128
#define H_   1039
#define KN   6          // max neighbors
#define KT   7          // center + neighbors
#define KDIM (CIN*KT)   // 448

// Static device scratch (allocation-guard safe)
__device__ float g_xt[(size_t)H_ * CIN * B_];      // xt[h][c][b]   ~68 MB
__device__ float g_wpack[KDIM * COUT];             // Wpack[ck][o]  ~229 KB
__device__ float g_tmp[(size_t)H_ * COUT * B_];    // tmp[h][o][b]  ~136 MB

// ---------------------------------------------------------------------------
// Kernel 1: x[b][c][h] -> g_xt[h][c][b]  (tiled transpose per channel c)
// ---------------------------------------------------------------------------
__global__ void k_transpose_x(const float* __restrict__ x) {
    __shared__ float t[32][33];
    const int c  = blockIdx.z;
    const int h0 = blockIdx.x * 32;
    const int b0 = blockIdx.y * 32;
    const int tx = threadIdx.x, ty = threadIdx.y;

#pragma unroll
    for (int i = 0; i < 32; i += 8) {
        int h = h0 + tx;
        int b = b0 + ty + i;
        if (h < H_)
            t[ty + i][tx] = x[((size_t)b * CIN + c) * H_ + h];   // coalesced in h
    }
    __syncthreads();
#pragma unroll
    for (int i = 0; i < 32; i += 8) {
        int b = b0 + tx;
        int h = h0 + ty + i;
        if (h < H_)
            g_xt[((size_t)h * CIN + c) * B_ + b] = t[tx][ty + i]; // coalesced in b
    }
}

// ---------------------------------------------------------------------------
// Kernel 2: pack weights: Wpack[(k*64+c)*128 + o]
//   k==0 -> weight_center[o][c] ; k>0 -> weight_neighbors[o][c][k-1]
// ---------------------------------------------------------------------------
__global__ void k_pack_w(const float* __restrict__ wc, const float* __restrict__ wn) {
    int t = blockIdx.x * blockDim.x + threadIdx.x;
    if (t >= KDIM * COUT) return;
    int ck = t / COUT;
    int o  = t % COUT;
    int k  = ck / CIN;
    int c  = ck % CIN;
    float v = (k == 0) ? wc[o * CIN + c]
                       : wn[(o * CIN + c) * KN + (k - 1)];
    g_wpack[t] = v;
}

// ---------------------------------------------------------------------------
// Packed f32x2 helpers (FFMA2 — ptxas won't auto-fuse; must go through PTX)
// ---------------------------------------------------------------------------
__device__ __forceinline__ unsigned long long pk2(float lo, float hi) {
    unsigned long long r;
    asm("mov.b64 %0, {%1, %2};" : "=l"(r) : "f"(lo), "f"(hi));
    return r;
}
__device__ __forceinline__ void fma2(unsigned long long& d,
                                     unsigned long long a, unsigned long long b) {
    asm("fma.rn.f32x2 %0, %1, %2, %0;" : "+l"(d) : "l"(a), "l"(b));
}
__device__ __forceinline__ float2 upk2(unsigned long long v) {
    float2 r;
    asm("mov.b64 {%0, %1}, %2;" : "=f"(r.x), "=f"(r.y) : "l"(v));
    return r;
}

// ---------------------------------------------------------------------------
// Kernel 3: per (h, b-half) GEMM: tmp[h][o][b0:b0+128] =
//           (Xg[b,448] @ Wpack^T) * (1/tv[h]) + bias
// Block: 256 threads, tile 128(b) x 128(o), K-chunk 32. 8x8 micro-tile/thread.
// ---------------------------------------------------------------------------
__global__ void __launch_bounds__(256, 2)
k_main(const int* __restrict__ neighbors, const float* __restrict__ bias) {
    __shared__ float Xs[32][128];   // [c_local][b_local]
    __shared__ float Ws[32][128];   // [c_local][o]
    __shared__ int   s_idx[KT];
    __shared__ float s_mask[KT];
    __shared__ float s_scale;

    const int h   = blockIdx.y;
    const int bm  = blockIdx.x * 128;
    const int tid = threadIdx.x;
    const int tx  = tid & 15;   // b direction
    const int ty  = tid >> 4;   // o direction

    if (tid == 0) {
        s_idx[0]  = h;
        s_mask[0] = 1.0f;
        int cnt = 1;
        for (int k = 1; k < KT; ++k) {
            int n = neighbors[h * KN + (k - 1)];
            bool v = (n >= 0);
            s_idx[k]  = v ? n : 0;
            s_mask[k] = v ? 1.0f : 0.0f;
            cnt += v ? 1 : 0;
        }
        s_scale = 1.0f / (float)cnt;
    }

    unsigned long long acc[8][4];
#pragma unroll
    for (int i = 0; i < 8; ++i)
#pragma unroll
        for (int j = 0; j < 4; ++j) acc[i][j] = 0ull;

    for (int kk = 0; kk < 2 * KT; ++kk) {
        const int k  = kk >> 1;
        const int c0 = (kk & 1) * 32;

        __syncthreads();   // also covers s_idx init on first iter

        const float  msk  = s_mask[k];
        const float* xsrc = g_xt + (size_t)s_idx[k] * (CIN * B_) + (size_t)c0 * B_ + bm;
        const float* wsrc = g_wpack + (size_t)(k * CIN + c0) * COUT;

#pragma unroll
        for (int i = 0; i < 4; ++i) {
            int id = tid + i * 256;          // 0..1023
            int r  = id >> 5;                // c_local 0..31
            int cv = id & 31;                // float4 index within 128
            float4 v = *(const float4*)(xsrc + (size_t)r * B_ + cv * 4);
            v.x *= msk; v.y *= msk; v.z *= msk; v.w *= msk;
            *(float4*)&Xs[r][cv * 4] = v;
            *(float4*)&Ws[r][cv * 4] = *(const float4*)(wsrc + id * 4);
        }
        __syncthreads();

#pragma unroll 4
        for (int ck = 0; ck < 32; ++ck) {
            float4 xb0 = *(const float4*)&Xs[ck][tx * 8];
            float4 xb1 = *(const float4*)&Xs[ck][tx * 8 + 4];
            float4 wa0 = *(const float4*)&Ws[ck][ty * 8];
            float4 wa1 = *(const float4*)&Ws[ck][ty * 8 + 4];

            unsigned long long xp[4];
            xp[0] = pk2(xb0.x, xb0.y);
            xp[1] = pk2(xb0.z, xb0.w);
            xp[2] = pk2(xb1.x, xb1.y);
            xp[3] = pk2(xb1.z, xb1.w);

            float wv[8] = {wa0.x, wa0.y, wa0.z, wa0.w, wa1.x, wa1.y, wa1.z, wa1.w};
#pragma unroll
            for (int i = 0; i < 8; ++i) {
                unsigned long long wd = pk2(wv[i], wv[i]);
#pragma unroll
                for (int j = 0; j < 4; ++j) fma2(acc[i][j], xp[j], wd);
            }
        }
    }

    // Epilogue: scale, bias, store to tmp[h][o][b] (coalesced in b)
    const float sc = s_scale;
    const int obase = ty * 8;
    const int bb    = bm + tx * 8;
#pragma unroll
    for (int i = 0; i < 8; ++i) {
        const int o = obase + i;
        const float bi = bias[o];
        float ov[8];
#pragma unroll
        for (int j = 0; j < 4; ++j) {
            float2 v = upk2(acc[i][j]);
            ov[2 * j]     = v.x * sc + bi;
            ov[2 * j + 1] = v.y * sc + bi;
        }
        float* dst = g_tmp + ((size_t)h * COUT + o) * B_ + bb;
        *(float4*)dst       = make_float4(ov[0], ov[1], ov[2], ov[3]);
        *(float4*)(dst + 4) = make_float4(ov[4], ov[5], ov[6], ov[7]);
    }
}

// ---------------------------------------------------------------------------
// Kernel 4: tmp[h][o][b] -> out[b][o][h]  (tiled transpose per o)
// ---------------------------------------------------------------------------
__global__ void k_transpose_out(float* __restrict__ out) {
    __shared__ float t[32][33];
    const int o  = blockIdx.z;
    const int h0 = blockIdx.x * 32;
    const int b0 = blockIdx.y * 32;
    const int tx = threadIdx.x, ty = threadIdx.y;

#pragma unroll
    for (int i = 0; i < 32; i += 8) {
        int b = b0 + tx;
        int h = h0 + ty + i;
        if (h < H_)
            t[ty + i][tx] = g_tmp[((size_t)h * COUT + o) * B_ + b];  // coalesced in b
    }
    __syncthreads();
#pragma unroll
    for (int i = 0; i < 32; i += 8) {
        int h = h0 + tx;
        int b = b0 + ty + i;
        if (h < H_)
            out[((size_t)b * COUT + o) * H_ + h] = t[tx][ty + i];    // coalesced in h
    }
}

// ---------------------------------------------------------------------------
// Launch
// Inputs (metadata order): x[f32], neighbors[int32], weight_center[f32],
//                          weight_neighbors[f32], bias[f32]
// ---------------------------------------------------------------------------
extern "C" void kernel_launch(void* const* d_in, const int* in_sizes, int n_in,
                              void* d_out, int out_size) {
    const float* x    = (const float*)d_in[0];
    const int*   nb   = (const int*)d_in[1];
    const float* wc   = (const float*)d_in[2];
    const float* wn   = (const float*)d_in[3];
    const float* bias = (const float*)d_in[4];
    float* out = (float*)d_out;

    // 1) transpose x -> xt[h][c][b]
    k_transpose_x<<<dim3((H_ + 31) / 32, B_ / 32, CIN), dim3(32, 8)>>>(x);

    // 2) pack weights
    k_pack_w<<<(KDIM * COUT + 1023) / 1024, 1024>>>(wc, wn);

    // 3) main GEMM per (b-half, h)
    k_main<<<dim3(2, H_), 256>>>(nb, bias);

    // 4) transpose tmp -> out
    k_transpose_out<<<dim3((H_ + 31) / 32, B_ / 32, COUT), dim3(32, 8)>>>(out);
}

// round 3
// speedup vs baseline: 2.1819x; 2.1819x over previous
#include <cuda_runtime.h>
#include <cuda_bf16.h>
#include <cstdint>

// Problem constants
#define B_   256
#define CIN  64
#define COUT 128
#define H_   1039
#define KN   6          // max neighbors
#define KT   7          // center + neighbors

// Static device scratch (allocation-guard safe)
__device__ __align__(256) __nv_bfloat16 g_xh[(size_t)H_ * B_ * CIN]; // [h][b][c] hi
__device__ __align__(256) __nv_bfloat16 g_xl[(size_t)H_ * B_ * CIN]; // [h][b][c] lo
__device__ __align__(256) __nv_bfloat16 g_wh[KT * COUT * CIN];       // [k][o][c] hi
__device__ __align__(256) __nv_bfloat16 g_wl[KT * COUT * CIN];       // [k][o][c] lo
__device__ __align__(256) float g_tmp[(size_t)H_ * COUT * B_];       // [h][o][b]

// ---------------------------------------------------------------------------
// PTX helpers (baseline ISA only — target lowers through compute_103, so no
// tcgen05/arch-'a' features)
// ---------------------------------------------------------------------------
__device__ __forceinline__ uint32_t smem_u32(const void* p) {
    uint32_t r;
    asm("{ .reg .u64 t; cvta.to.shared.u64 t, %1; cvt.u32.u64 %0, t; }"
        : "=r"(r) : "l"(p));
    return r;
}
__device__ __forceinline__ void cpasync16(uint32_t s, const void* g) {
    asm volatile("cp.async.ca.shared.global [%0], [%1], 16;"
                 :: "r"(s), "l"(g) : "memory");
}
#define CP_COMMIT() asm volatile("cp.async.commit_group;" ::: "memory")
#define CP_WAIT(n)  asm volatile("cp.async.wait_group %0;" :: "n"(n) : "memory")

#define LDSM_X4(r, addr) \
    asm volatile("ldmatrix.sync.aligned.m8n8.x4.shared.b16 {%0,%1,%2,%3}, [%4];" \
                 : "=r"((r)[0]), "=r"((r)[1]), "=r"((r)[2]), "=r"((r)[3]) \
                 : "r"(addr))

__device__ __forceinline__ void mma_bf16(float* c, const uint32_t* a,
                                         uint32_t b0, uint32_t b1) {
    asm volatile(
        "mma.sync.aligned.m16n8k16.row.col.f32.bf16.bf16.f32 "
        "{%0,%1,%2,%3}, {%4,%5,%6,%7}, {%8,%9}, {%0,%1,%2,%3};"
        : "+f"(c[0]), "+f"(c[1]), "+f"(c[2]), "+f"(c[3])
        : "r"(a[0]), "r"(a[1]), "r"(a[2]), "r"(a[3]), "r"(b0), "r"(b1));
}

// ---------------------------------------------------------------------------
// Kernel 1: x[b][c][h] (viewed [m=bc][h]) -> g_xh/g_xl [h][m]  bf16 hi/lo split
// ---------------------------------------------------------------------------
__global__ void k_prep_x(const float* __restrict__ x) {
    __shared__ float t[32][33];
    const int h0 = blockIdx.x * 32;
    const int m0 = blockIdx.y * 32;
    const int tx = threadIdx.x, ty = threadIdx.y;

#pragma unroll
    for (int i = 0; i < 32; i += 8) {
        int h = h0 + tx;
        if (h < H_)
            t[ty + i][tx] = x[(size_t)(m0 + ty + i) * H_ + h];
    }
    __syncthreads();
#pragma unroll
    for (int i = 0; i < 32; i += 8) {
        int h = h0 + ty + i;
        int m = m0 + tx;
        if (h < H_) {
            float v = t[tx][ty + i];
            __nv_bfloat16 hi = __float2bfloat16(v);
            __nv_bfloat16 lo = __float2bfloat16(v - __bfloat162float(hi));
            size_t idx = (size_t)h * (B_ * CIN) + m;
            g_xh[idx] = hi;
            g_xl[idx] = lo;
        }
    }
}

// ---------------------------------------------------------------------------
// Kernel 2: pack + split weights: g_wh/g_wl[k][o][c]
// ---------------------------------------------------------------------------
__global__ void k_pack_w(const float* __restrict__ wc, const float* __restrict__ wn) {
    int t = blockIdx.x * blockDim.x + threadIdx.x;
    if (t >= KT * COUT * CIN) return;
    int k = t / (COUT * CIN);
    int o = (t / CIN) % COUT;
    int c = t % CIN;
    float v = (k == 0) ? wc[o * CIN + c]
                       : wn[(o * CIN + c) * KN + (k - 1)];
    __nv_bfloat16 hi = __float2bfloat16(v);
    __nv_bfloat16 lo = __float2bfloat16(v - __bfloat162float(hi));
    g_wh[t] = hi;
    g_wl[t] = lo;
}

// ---------------------------------------------------------------------------
// Kernel 3: main HMMA GEMM. One CTA (8 warps) per hexagon h.
// D[o=128][b=256] = sum over valid chunks of W_k[128,64] . X_k[256,64]^T
// bf16 3-term split (hh + lh + hl), fp32 accumulators.
// cp.async double-buffered stages, XOR-swizzled SMEM, ldmatrix + mma.sync.
// ---------------------------------------------------------------------------
// Stage layout: Ah(16K) Al(16K) Bh(32K) Bl(32K) = 96K; 2 stages = 192K
#define A_BYTES 16384
#define B_BYTES 32768
#define STAGE_BYTES (2 * A_BYTES + 2 * B_BYTES)
#define DSMEM_BYTES (2 * STAGE_BYTES + 1024)

extern __shared__ char dsm[];

// swizzled smem offset for (row, 16B-chunk c) within a tile of 128B rows
__device__ __forceinline__ uint32_t swz(uint32_t row, uint32_t c) {
    return row * 128u + ((c ^ (row & 7u)) * 16u);
}

__global__ void __launch_bounds__(256, 1)
k_main(const int* __restrict__ neighbors, const float* __restrict__ bias) {
    __shared__ int s_idx[KT];
    __shared__ int s_n;
    __shared__ float s_scale;

    const int h    = blockIdx.x;
    const int tid  = threadIdx.x;
    const int wid  = tid >> 5;
    const int lane = tid & 31;
    const int wo   = wid & 1;   // o-half (64)
    const int wb   = wid >> 1;  // b-quarter (64)

    const uint32_t sraw  = smem_u32(dsm);
    const uint32_t sbase = (sraw + 1023u) & ~1023u;

    if (tid == 0) {
        s_idx[0] = h;
        int n = 1;
#pragma unroll
        for (int k = 0; k < KN; ++k) {
            int v = neighbors[h * KN + k];
            if (v >= 0) s_idx[n++] = v;
        }
        s_n = n;
        s_scale = 1.0f / (float)n;
    }
    __syncthreads();

    const int n = s_n;

    // ---- stage loader: chunk ci -> buffer j ----
    auto load_stage = [&](int ci, int j) {
        const int hidx = s_idx[ci];
        const char* Ah = (const char*)(g_wh + (size_t)ci * (COUT * CIN));
        const char* Al = (const char*)(g_wl + (size_t)ci * (COUT * CIN));
        const char* Bh = (const char*)(g_xh + (size_t)hidx * (B_ * CIN));
        const char* Bl = (const char*)(g_xl + (size_t)hidx * (B_ * CIN));
        const uint32_t sb = sbase + (uint32_t)j * STAGE_BYTES;
#pragma unroll
        for (int p = 0; p < 4; ++p) {                 // A tiles: 1024 chunks each
            int id = tid + p * 256;
            uint32_t sw = swz((uint32_t)(id >> 3), (uint32_t)(id & 7));
            cpasync16(sb + sw,            Ah + (size_t)id * 16);
            cpasync16(sb + A_BYTES + sw,  Al + (size_t)id * 16);
        }
#pragma unroll
        for (int p = 0; p < 8; ++p) {                 // B tiles: 2048 chunks each
            int id = tid + p * 256;
            uint32_t sw = swz((uint32_t)(id >> 3), (uint32_t)(id & 7));
            cpasync16(sb + 2 * A_BYTES + sw,           Bh + (size_t)id * 16);
            cpasync16(sb + 2 * A_BYTES + B_BYTES + sw, Bl + (size_t)id * 16);
        }
    };

    float acc[4][8][4];
#pragma unroll
    for (int mi = 0; mi < 4; ++mi)
#pragma unroll
        for (int ni = 0; ni < 8; ++ni)
#pragma unroll
            for (int q = 0; q < 4; ++q) acc[mi][ni][q] = 0.0f;

    load_stage(0, 0);
    CP_COMMIT();

    // ldmatrix lane address components
    const uint32_t a_lr = (uint32_t)(lane & 15);
    const uint32_t a_lc = (uint32_t)(lane >> 4);
    const uint32_t b_lr = (uint32_t)((lane & 7) + ((lane & 16) >> 1)); // 0..15
    const uint32_t b_lc = (uint32_t)((lane >> 3) & 1);

    for (int i = 0; i < n; ++i) {
        const int j = i & 1;
        if (i + 1 < n) {
            load_stage(i + 1, j ^ 1);
            CP_COMMIT();
            CP_WAIT(1);
        } else {
            CP_WAIT(0);
        }
        __syncthreads();

        const uint32_t st = sbase + (uint32_t)j * STAGE_BYTES;
        const uint32_t Asel[3] = { st, st + A_BYTES, st };                      // hh, lh, hl
        const uint32_t Bsel[3] = { st + 2 * A_BYTES, st + 2 * A_BYTES,
                                   st + 2 * A_BYTES + B_BYTES };

#pragma unroll
        for (int t = 0; t < 3; ++t) {
            const uint32_t Ab = Asel[t];
            const uint32_t Bb = Bsel[t];
#pragma unroll
            for (int ks = 0; ks < 4; ++ks) {
                uint32_t a[4][4];
#pragma unroll
                for (int mi = 0; mi < 4; ++mi) {
                    uint32_t row = (uint32_t)(wo * 64 + mi * 16) + a_lr;
                    LDSM_X4(a[mi], Ab + swz(row, (uint32_t)(ks * 2) + a_lc));
                }
                uint32_t b[4][4];
#pragma unroll
                for (int nt = 0; nt < 4; ++nt) {
                    uint32_t row = (uint32_t)(wb * 64 + nt * 16) + b_lr;
                    LDSM_X4(b[nt], Bb + swz(row, (uint32_t)(ks * 2) + b_lc));
                }
#pragma unroll
                for (int mi = 0; mi < 4; ++mi)
#pragma unroll
                    for (int nt = 0; nt < 4; ++nt) {
                        mma_bf16(acc[mi][2 * nt],     a[mi], b[nt][0], b[nt][1]);
                        mma_bf16(acc[mi][2 * nt + 1], a[mi], b[nt][2], b[nt][3]);
                    }
            }
        }
        __syncthreads();
    }

    // ---- epilogue: scale + bias, write g_tmp[h][o][b] ----
    const float sc = s_scale;
    const int r     = lane >> 2;
    const int cpair = (lane & 3) * 2;
#pragma unroll
    for (int mi = 0; mi < 4; ++mi) {
        const int o0 = wo * 64 + mi * 16 + r;
        const float bi0 = bias[o0];
        const float bi8 = bias[o0 + 8];
        float* d0 = g_tmp + ((size_t)h * COUT + o0) * B_ + wb * 64 + cpair;
        float* d8 = d0 + 8 * B_;
#pragma unroll
        for (int ni = 0; ni < 8; ++ni) {
            float2 v0, v8;
            v0.x = acc[mi][ni][0] * sc + bi0;
            v0.y = acc[mi][ni][1] * sc + bi0;
            v8.x = acc[mi][ni][2] * sc + bi8;
            v8.y = acc[mi][ni][3] * sc + bi8;
            *(float2*)(d0 + ni * 8) = v0;
            *(float2*)(d8 + ni * 8) = v8;
        }
    }
}

// ---------------------------------------------------------------------------
// Kernel 4: tmp[h][o][b] -> out[b][o][h]  (tiled transpose per o)
// ---------------------------------------------------------------------------
__global__ void k_transpose_out(float* __restrict__ out) {
    __shared__ float t[32][33];
    const int o  = blockIdx.z;
    const int h0 = blockIdx.x * 32;
    const int b0 = blockIdx.y * 32;
    const int tx = threadIdx.x, ty = threadIdx.y;

#pragma unroll
    for (int i = 0; i < 32; i += 8) {
        int b = b0 + tx;
        int hh = h0 + ty + i;
        if (hh < H_)
            t[ty + i][tx] = g_tmp[((size_t)hh * COUT + o) * B_ + b];
    }
    __syncthreads();
#pragma unroll
    for (int i = 0; i < 32; i += 8) {
        int hh = h0 + tx;
        int b = b0 + ty + i;
        if (hh < H_)
            out[((size_t)b * COUT + o) * H_ + hh] = t[tx][ty + i];
    }
}

// ---------------------------------------------------------------------------
// Launch
// Inputs: x[f32], neighbors[int32], weight_center[f32], weight_neighbors[f32],
//         bias[f32]
// ---------------------------------------------------------------------------
extern "C" void kernel_launch(void* const* d_in, const int* in_sizes, int n_in,
                              void* d_out, int out_size) {
    const float* x    = (const float*)d_in[0];
    const int*   nb   = (const int*)d_in[1];
    const float* wc   = (const float*)d_in[2];
    const float* wn   = (const float*)d_in[3];
    const float* bias = (const float*)d_in[4];
    float* out = (float*)d_out;

    // 1) transpose + bf16 hi/lo split of x
    k_prep_x<<<dim3((H_ + 31) / 32, (B_ * CIN) / 32), dim3(32, 8)>>>(x);

    // 2) pack + split weights
    k_pack_w<<<(KT * COUT * CIN + 255) / 256, 256>>>(wc, wn);

    // 3) main HMMA GEMM, one CTA per hexagon
    cudaFuncSetAttribute(k_main, cudaFuncAttributeMaxDynamicSharedMemorySize,
                         DSMEM_BYTES);
    k_main<<<H_, 256, DSMEM_BYTES>>>(nb, bias);

    // 4) transpose tmp -> out
    k_transpose_out<<<dim3((H_ + 31) / 32, B_ / 32, COUT), dim3(32, 8)>>>(out);
}

// round 4
// speedup vs baseline: 2.8393x; 1.3013x over previous
#include <cuda_runtime.h>
#include <cuda_fp16.h>
#include <cstdint>

// Problem constants
#define B_   256
#define CIN  64
#define COUT 128
#define H_   1039
#define KN   6          // max neighbors
#define KT   7          // center + neighbors

// Static device scratch (allocation-guard safe)
__device__ __align__(256) __half g_xh[(size_t)H_ * B_ * CIN];   // [h][b][c] hi
__device__ __align__(256) __half g_xl[(size_t)H_ * B_ * CIN];   // [h][b][c] lo
__device__ __align__(256) __half g_wfrag[KT * COUT * CIN];      // fragment-order fp16
__device__ __align__(256) float  g_tmp[(size_t)H_ * COUT * B_]; // [h][o][b]

// ---------------------------------------------------------------------------
// PTX helpers (baseline ISA only — toolchain lowers through compute_103)
// ---------------------------------------------------------------------------
__device__ __forceinline__ uint32_t smem_u32(const void* p) {
    uint32_t r;
    asm("{ .reg .u64 t; cvta.to.shared.u64 t, %1; cvt.u32.u64 %0, t; }"
        : "=r"(r) : "l"(p));
    return r;
}
__device__ __forceinline__ void cpasync16(uint32_t s, const void* g) {
    asm volatile("cp.async.ca.shared.global [%0], [%1], 16;"
                 :: "r"(s), "l"(g) : "memory");
}
#define CP_COMMIT() asm volatile("cp.async.commit_group;" ::: "memory")
#define CP_WAIT(n)  asm volatile("cp.async.wait_group %0;" :: "n"(n) : "memory")

#define LDSM_X4(r, addr) \
    asm volatile("ldmatrix.sync.aligned.m8n8.x4.shared.b16 {%0,%1,%2,%3}, [%4];" \
                 : "=r"((r)[0]), "=r"((r)[1]), "=r"((r)[2]), "=r"((r)[3]) \
                 : "r"(addr))

__device__ __forceinline__ void mma_fp16(float* c, const uint32_t* a,
                                         uint32_t b0, uint32_t b1) {
    asm volatile(
        "mma.sync.aligned.m16n8k16.row.col.f32.f16.f16.f32 "
        "{%0,%1,%2,%3}, {%4,%5,%6,%7}, {%8,%9}, {%0,%1,%2,%3};"
        : "+f"(c[0]), "+f"(c[1]), "+f"(c[2]), "+f"(c[3])
        : "r"(a[0]), "r"(a[1]), "r"(a[2]), "r"(a[3]), "r"(b0), "r"(b1));
}

// ---------------------------------------------------------------------------
// Kernel 1: x[b][c][h] (viewed [m=bc][h]) -> g_xh/g_xl [h][m]  fp16 hi/lo split
// ---------------------------------------------------------------------------
__global__ void k_prep_x(const float* __restrict__ x) {
    __shared__ float t[32][33];
    const int h0 = blockIdx.x * 32;
    const int m0 = blockIdx.y * 32;
    const int tx = threadIdx.x, ty = threadIdx.y;

#pragma unroll
    for (int i = 0; i < 32; i += 8) {
        int h = h0 + tx;
        if (h < H_)
            t[ty + i][tx] = x[(size_t)(m0 + ty + i) * H_ + h];
    }
    __syncthreads();
#pragma unroll
    for (int i = 0; i < 32; i += 8) {
        int h = h0 + ty + i;
        int m = m0 + tx;
        if (h < H_) {
            float v = t[tx][ty + i];
            __half hi = __float2half(v);
            __half lo = __float2half(v - __half2float(hi));
            size_t idx = (size_t)h * (B_ * CIN) + m;
            g_xh[idx] = hi;
            g_xl[idx] = lo;
        }
    }
}

// ---------------------------------------------------------------------------
// Kernel 2: pack weights into per-lane MMA fragment order (fp16, hi only).
// 16B lane-chunk layout: addr16 = ((k*8 + mi)*4 + ks)*32 + lane; 8 halves/lane:
//   e = j*2 + hh (j = mma A reg 0..3)
//   row(o) = mi*16 + (j&1)*8 + (lane>>2)
//   col(c) = ks*16 + ((j>>1)&1)*8 + (lane&3)*2 + hh
// ---------------------------------------------------------------------------
__global__ void k_pack_w(const float* __restrict__ wc, const float* __restrict__ wn) {
    int t = blockIdx.x * blockDim.x + threadIdx.x;
    if (t >= KT * COUT * CIN) return;
    int k    = t >> 13;           // /8192
    int rem  = t & 8191;
    int mi   = rem >> 10;         // /1024
    int rem2 = rem & 1023;
    int ks   = rem2 >> 8;
    int rem3 = rem2 & 255;
    int ln   = rem3 >> 3;
    int e    = rem3 & 7;
    int j    = e >> 1;
    int hh   = e & 1;
    int o = mi * 16 + (j & 1) * 8 + (ln >> 2);
    int c = ks * 16 + ((j >> 1) & 1) * 8 + (ln & 3) * 2 + hh;
    float v = (k == 0) ? wc[o * CIN + c]
                       : wn[(o * CIN + c) * KN + (k - 1)];
    g_wfrag[t] = __float2half(v);
}

// ---------------------------------------------------------------------------
// Kernel 3: main HMMA GEMM. One CTA (8 warps) per hexagon h.
// D[o=128][b=256] = sum over valid chunks i of W_i[128,64] . X_i[256,64]^T
// fp16 2-term split (xh*wh + xl*wh), fp32 accumulators.
// B-only smem stages (Bh 32K + Bl 32K), 3-stage cp.async ring, one barrier
// per chunk. A fragments LDG'd from L1-resident pre-packed weights.
// ---------------------------------------------------------------------------
#define BT_BYTES 32768
#define STAGE_BYTES (2 * BT_BYTES)          // 64 KB
#define NSTAGE 3
#define DSMEM_BYTES (NSTAGE * STAGE_BYTES + 1024)

extern __shared__ char dsm[];

// swizzled smem offset for (row, 16B-chunk c) within a tile of 128B rows
__device__ __forceinline__ uint32_t swz(uint32_t row, uint32_t c) {
    return row * 128u + ((c ^ (row & 7u)) * 16u);
}

__global__ void __launch_bounds__(256, 1)
k_main(const int* __restrict__ neighbors, const float* __restrict__ bias) {
    __shared__ int s_idx[KT];
    __shared__ int s_n;
    __shared__ float s_scale;

    const int h    = blockIdx.x;
    const int tid  = threadIdx.x;
    const int wid  = tid >> 5;
    const int lane = tid & 31;
    const int wo   = wid & 1;   // o-half (64)
    const int wb   = wid >> 1;  // b-quarter (64)

    const uint32_t sraw  = smem_u32(dsm);
    const uint32_t sbase = (sraw + 1023u) & ~1023u;

    if (tid == 0) {
        s_idx[0] = h;
        int n = 1;
#pragma unroll
        for (int k = 0; k < KN; ++k) {
            int v = neighbors[h * KN + k];
            if (v >= 0) s_idx[n++] = v;   // valid-prefix layout: slot k -> weight k+1
        }
        s_n = n;
        s_scale = 1.0f / (float)n;
    }
    __syncthreads();

    const int n = s_n;

    // ---- stage loader: chunk ci -> ring buffer j ----
    auto load_stage = [&](int ci, int j) {
        const int hidx = s_idx[ci];
        const char* Bh = (const char*)(g_xh + (size_t)hidx * (B_ * CIN));
        const char* Bl = (const char*)(g_xl + (size_t)hidx * (B_ * CIN));
        const uint32_t sb = sbase + (uint32_t)j * STAGE_BYTES;
#pragma unroll
        for (int p = 0; p < 8; ++p) {             // 2048 16B chunks per tile
            int id = tid + p * 256;
            uint32_t sw = swz((uint32_t)(id >> 3), (uint32_t)(id & 7));
            cpasync16(sb + sw,            Bh + (size_t)id * 16);
            cpasync16(sb + BT_BYTES + sw, Bl + (size_t)id * 16);
        }
    };

    float acc[4][8][4];
#pragma unroll
    for (int mi = 0; mi < 4; ++mi)
#pragma unroll
        for (int ni = 0; ni < 8; ++ni)
#pragma unroll
            for (int q = 0; q < 4; ++q) acc[mi][ni][q] = 0.0f;

    load_stage(0, 0); CP_COMMIT();
    load_stage(1, 1); CP_COMMIT();

    // ldmatrix lane address components for B (same mapping verified in R3)
    const uint32_t b_lr = (uint32_t)((lane & 7) + ((lane & 16) >> 1)); // 0..15
    const uint32_t b_lc = (uint32_t)((lane >> 3) & 1);

    const uint4* __restrict__ wf = (const uint4*)g_wfrag;

    for (int i = 0; i < n; ++i) {
        if (i < n - 1) { CP_WAIT(1); } else { CP_WAIT(0); }
        __syncthreads();            // stage i visible; all warps done with chunk i-1

        if (i + 2 < n) { load_stage(i + 2, (i + 2) % NSTAGE); CP_COMMIT(); }

        const uint32_t st = sbase + (uint32_t)(i % NSTAGE) * STAGE_BYTES;
        // weight chunk index == i (valid-prefix neighbor layout)
        const uint4* wfk = wf + (size_t)i * 1024;   // 8192 halves = 1024 uint4

#pragma unroll
        for (int ks = 0; ks < 4; ++ks) {
            // A fragments: direct LDG from L1-resident packed weights
            uint32_t a[4][4];
#pragma unroll
            for (int mi = 0; mi < 4; ++mi) {
                uint4 v = wfk[(((wo * 4 + mi) * 4 + ks) * 32) + lane];
                a[mi][0] = v.x; a[mi][1] = v.y; a[mi][2] = v.z; a[mi][3] = v.w;
            }
#pragma unroll
            for (int t = 0; t < 2; ++t) {          // t=0: xh, t=1: xl
                const uint32_t Bb = st + (uint32_t)t * BT_BYTES;
                uint32_t b[4][4];
#pragma unroll
                for (int nt = 0; nt < 4; ++nt) {
                    uint32_t row = (uint32_t)(wb * 64 + nt * 16) + b_lr;
                    LDSM_X4(b[nt], Bb + swz(row, (uint32_t)(ks * 2) + b_lc));
                }
#pragma unroll
                for (int mi = 0; mi < 4; ++mi)
#pragma unroll
                    for (int nt = 0; nt < 4; ++nt) {
                        mma_fp16(acc[mi][2 * nt],     a[mi], b[nt][0], b[nt][1]);
                        mma_fp16(acc[mi][2 * nt + 1], a[mi], b[nt][2], b[nt][3]);
                    }
            }
        }
    }

    // ---- epilogue: scale + bias, write g_tmp[h][o][b] ----
    const float sc = s_scale;
    const int r     = lane >> 2;
    const int cpair = (lane & 3) * 2;
#pragma unroll
    for (int mi = 0; mi < 4; ++mi) {
        const int o0 = wo * 64 + mi * 16 + r;
        const float bi0 = bias[o0];
        const float bi8 = bias[o0 + 8];
        float* d0 = g_tmp + ((size_t)h * COUT + o0) * B_ + wb * 64 + cpair;
        float* d8 = d0 + 8 * B_;
#pragma unroll
        for (int ni = 0; ni < 8; ++ni) {
            float2 v0, v8;
            v0.x = acc[mi][ni][0] * sc + bi0;
            v0.y = acc[mi][ni][1] * sc + bi0;
            v8.x = acc[mi][ni][2] * sc + bi8;
            v8.y = acc[mi][ni][3] * sc + bi8;
            *(float2*)(d0 + ni * 8) = v0;
            *(float2*)(d8 + ni * 8) = v8;
        }
    }
}

// ---------------------------------------------------------------------------
// Kernel 4: tmp[h][o][b] -> out[b][o][h]  (tiled transpose per o)
// ---------------------------------------------------------------------------
__global__ void k_transpose_out(float* __restrict__ out) {
    __shared__ float t[32][33];
    const int o  = blockIdx.z;
    const int h0 = blockIdx.x * 32;
    const int b0 = blockIdx.y * 32;
    const int tx = threadIdx.x, ty = threadIdx.y;

#pragma unroll
    for (int i = 0; i < 32; i += 8) {
        int b = b0 + tx;
        int hh = h0 + ty + i;
        if (hh < H_)
            t[ty + i][tx] = g_tmp[((size_t)hh * COUT + o) * B_ + b];
    }
    __syncthreads();
#pragma unroll
    for (int i = 0; i < 32; i += 8) {
        int hh = h0 + tx;
        int b = b0 + ty + i;
        if (hh < H_)
            out[((size_t)b * COUT + o) * H_ + hh] = t[tx][ty + i];
    }
}

// ---------------------------------------------------------------------------
// Launch
// Inputs: x[f32], neighbors[int32], weight_center[f32], weight_neighbors[f32],
//         bias[f32]
// ---------------------------------------------------------------------------
extern "C" void kernel_launch(void* const* d_in, const int* in_sizes, int n_in,
                              void* d_out, int out_size) {
    const float* x    = (const float*)d_in[0];
    const int*   nb   = (const int*)d_in[1];
    const float* wc   = (const float*)d_in[2];
    const float* wn   = (const float*)d_in[3];
    const float* bias = (const float*)d_in[4];
    float* out = (float*)d_out;

    // 1) transpose + fp16 hi/lo split of x
    k_prep_x<<<dim3((H_ + 31) / 32, (B_ * CIN) / 32), dim3(32, 8)>>>(x);

    // 2) pack weights into fragment order
    k_pack_w<<<(KT * COUT * CIN + 255) / 256, 256>>>(wc, wn);

    // 3) main HMMA GEMM, one CTA per hexagon
    cudaFuncSetAttribute(k_main, cudaFuncAttributeMaxDynamicSharedMemorySize,
                         DSMEM_BYTES);
    k_main<<<H_, 256, DSMEM_BYTES>>>(nb, bias);

    // 4) transpose tmp -> out
    k_transpose_out<<<dim3((H_ + 31) / 32, B_ / 32, COUT), dim3(32, 8)>>>(out);
}

// round 5
// speedup vs baseline: 4.1019x; 1.4447x over previous
#include <cuda_runtime.h>
#include <cuda_fp16.h>
#include <cstdint>

// Problem constants
#define B_   256
#define CIN  64
#define COUT 128
#define H_   1039
#define KN   6          // max neighbors
#define KT   7          // center + neighbors

// Static device scratch (allocation-guard safe)
__device__ __align__(256) __half g_x[(size_t)H_ * B_ * CIN];    // [h][b][c] fp16
__device__ __align__(256) __half g_wfrag[KT * COUT * CIN];      // fragment-order fp16
__device__ __align__(256) float  g_tmp[(size_t)H_ * COUT * B_]; // [h][o][b]

// ---------------------------------------------------------------------------
// PTX helpers (baseline ISA only — toolchain lowers through compute_103)
// ---------------------------------------------------------------------------
__device__ __forceinline__ uint32_t smem_u32(const void* p) {
    uint32_t r;
    asm("{ .reg .u64 t; cvta.to.shared.u64 t, %1; cvt.u32.u64 %0, t; }"
        : "=r"(r) : "l"(p));
    return r;
}
__device__ __forceinline__ void cpasync16(uint32_t s, const void* g) {
    asm volatile("cp.async.ca.shared.global [%0], [%1], 16;"
                 :: "r"(s), "l"(g) : "memory");
}
#define CP_COMMIT() asm volatile("cp.async.commit_group;" ::: "memory")
#define CP_WAIT(n)  asm volatile("cp.async.wait_group %0;" :: "n"(n) : "memory")

#define LDSM_X4(r, addr) \
    asm volatile("ldmatrix.sync.aligned.m8n8.x4.shared.b16 {%0,%1,%2,%3}, [%4];" \
                 : "=r"((r)[0]), "=r"((r)[1]), "=r"((r)[2]), "=r"((r)[3]) \
                 : "r"(addr))

__device__ __forceinline__ void mma_fp16(float* c, const uint32_t* a,
                                         uint32_t b0, uint32_t b1) {
    asm volatile(
        "mma.sync.aligned.m16n8k16.row.col.f32.f16.f16.f32 "
        "{%0,%1,%2,%3}, {%4,%5,%6,%7}, {%8,%9}, {%0,%1,%2,%3};"
        : "+f"(c[0]), "+f"(c[1]), "+f"(c[2]), "+f"(c[3])
        : "r"(a[0]), "r"(a[1]), "r"(a[2]), "r"(a[3]), "r"(b0), "r"(b1));
}

// ---------------------------------------------------------------------------
// Kernel 1: x[b][c][h] (viewed [m=bc][h]) -> g_x[h][m] fp16
// ---------------------------------------------------------------------------
__global__ void k_prep_x(const float* __restrict__ x) {
    __shared__ float t[32][33];
    const int h0 = blockIdx.x * 32;
    const int m0 = blockIdx.y * 32;
    const int tx = threadIdx.x, ty = threadIdx.y;

#pragma unroll
    for (int i = 0; i < 32; i += 8) {
        int h = h0 + tx;
        if (h < H_)
            t[ty + i][tx] = x[(size_t)(m0 + ty + i) * H_ + h];
    }
    __syncthreads();
#pragma unroll
    for (int i = 0; i < 32; i += 8) {
        int h = h0 + ty + i;
        int m = m0 + tx;
        if (h < H_)
            g_x[(size_t)h * (B_ * CIN) + m] = __float2half(t[tx][ty + i]);
    }
}

// ---------------------------------------------------------------------------
// Kernel 2: pack weights into per-lane MMA fragment order (fp16).
// addr16 = ((k*8 + MI)*4 + ks)*32 + lane; 8 halves per lane-chunk:
//   e = j*2 + hh (j = mma A reg 0..3)
//   row(o) = MI*16 + (j&1)*8 + (lane>>2)
//   col(c) = ks*16 + ((j>>1)&1)*8 + (lane&3)*2 + hh
// ---------------------------------------------------------------------------
__global__ void k_pack_w(const float* __restrict__ wc, const float* __restrict__ wn) {
    int t = blockIdx.x * blockDim.x + threadIdx.x;
    if (t >= KT * COUT * CIN) return;
    int k    = t >> 13;
    int rem  = t & 8191;
    int mi   = rem >> 10;
    int rem2 = rem & 1023;
    int ks   = rem2 >> 8;
    int rem3 = rem2 & 255;
    int ln   = rem3 >> 3;
    int e    = rem3 & 7;
    int j    = e >> 1;
    int hh   = e & 1;
    int o = mi * 16 + (j & 1) * 8 + (ln >> 2);
    int c = ks * 16 + ((j >> 1) & 1) * 8 + (ln & 3) * 2 + hh;
    float v = (k == 0) ? wc[o * CIN + c]
                       : wn[(o * CIN + c) * KN + (k - 1)];
    g_wfrag[t] = __float2half(v);
}

// ---------------------------------------------------------------------------
// Kernel 3: main HMMA GEMM. Grid (2 b-halves, H). CTA tile o=128 x b=128.
// 8 warps, warp tile 32(o) x 64(b). Single fp16 term, fp32 accumulate.
// 16KB B stages, 3-stage cp.async ring, one barrier per chunk, occupancy 2.
// A fragments LDG'd from L1-resident pre-packed weights.
// ---------------------------------------------------------------------------
#define BT_BYTES 16384                    // 128 rows x 128B
#define NSTAGE 3
#define DSMEM_BYTES (NSTAGE * BT_BYTES + 1024)

extern __shared__ char dsm[];

// swizzled smem offset for (row, 16B-chunk c) within a tile of 128B rows
__device__ __forceinline__ uint32_t swz(uint32_t row, uint32_t c) {
    return row * 128u + ((c ^ (row & 7u)) * 16u);
}

__global__ void __launch_bounds__(256, 2)
k_main(const int* __restrict__ neighbors, const float* __restrict__ bias) {
    __shared__ int s_idx[KT];
    __shared__ int s_n;
    __shared__ float s_scale;

    const int h    = blockIdx.y;
    const int bh   = blockIdx.x;          // b-half: rows bh*128 .. bh*128+127
    const int tid  = threadIdx.x;
    const int wid  = tid >> 5;
    const int lane = tid & 31;
    const int wo   = wid & 3;             // o-quarter (32 rows)
    const int wb   = wid >> 2;            // b 64-half within the 128

    const uint32_t sraw  = smem_u32(dsm);
    const uint32_t sbase = (sraw + 1023u) & ~1023u;

    if (tid == 0) {
        s_idx[0] = h;
        int n = 1;
#pragma unroll
        for (int k = 0; k < KN; ++k) {
            int v = neighbors[h * KN + k];
            if (v >= 0) s_idx[n++] = v;   // valid-prefix: slot i -> weight chunk i
        }
        s_n = n;
        s_scale = 1.0f / (float)n;
    }
    __syncthreads();

    const int n = s_n;
    const size_t boff = (size_t)bh * 128 * CIN;   // byte offset handled below

    // ---- stage loader: chunk ci -> ring buffer j (128 rows of this b-half) ----
    auto load_stage = [&](int ci, int j) {
        const char* Bsrc = (const char*)(g_x + (size_t)s_idx[ci] * (B_ * CIN) + boff);
        const uint32_t sb = sbase + (uint32_t)j * BT_BYTES;
#pragma unroll
        for (int p = 0; p < 4; ++p) {             // 1024 16B chunks
            int id = tid + p * 256;
            uint32_t sw = swz((uint32_t)(id >> 3), (uint32_t)(id & 7));
            cpasync16(sb + sw, Bsrc + (size_t)id * 16);
        }
    };

    float acc[2][8][4];
#pragma unroll
    for (int mi = 0; mi < 2; ++mi)
#pragma unroll
        for (int ni = 0; ni < 8; ++ni)
#pragma unroll
            for (int q = 0; q < 4; ++q) acc[mi][ni][q] = 0.0f;

    load_stage(0, 0); CP_COMMIT();
    load_stage(1, 1); CP_COMMIT();

    const uint32_t b_lr = (uint32_t)((lane & 7) + ((lane & 16) >> 1)); // 0..15
    const uint32_t b_lc = (uint32_t)((lane >> 3) & 1);

    const uint4* __restrict__ wf = (const uint4*)g_wfrag;

    for (int i = 0; i < n; ++i) {
        if (i < n - 1) { CP_WAIT(1); } else { CP_WAIT(0); }
        __syncthreads();

        if (i + 2 < n) { load_stage(i + 2, (i + 2) % NSTAGE); CP_COMMIT(); }

        const uint32_t st = sbase + (uint32_t)(i % NSTAGE) * BT_BYTES;
        const uint4* wfk = wf + (size_t)i * 1024;

#pragma unroll
        for (int ks = 0; ks < 4; ++ks) {
            uint32_t a[2][4];
#pragma unroll
            for (int mi = 0; mi < 2; ++mi) {
                int MI = wo * 2 + mi;                         // o-row group 0..7
                uint4 v = wfk[((MI * 4 + ks) * 32) + lane];
                a[mi][0] = v.x; a[mi][1] = v.y; a[mi][2] = v.z; a[mi][3] = v.w;
            }
            uint32_t b[4][4];
#pragma unroll
            for (int nt = 0; nt < 4; ++nt) {
                uint32_t row = (uint32_t)(wb * 64 + nt * 16) + b_lr;
                LDSM_X4(b[nt], st + swz(row, (uint32_t)(ks * 2) + b_lc));
            }
#pragma unroll
            for (int mi = 0; mi < 2; ++mi)
#pragma unroll
                for (int nt = 0; nt < 4; ++nt) {
                    mma_fp16(acc[mi][2 * nt],     a[mi], b[nt][0], b[nt][1]);
                    mma_fp16(acc[mi][2 * nt + 1], a[mi], b[nt][2], b[nt][3]);
                }
        }
    }

    // ---- epilogue: scale + bias, write g_tmp[h][o][b] ----
    const float sc = s_scale;
    const int r     = lane >> 2;
    const int cpair = (lane & 3) * 2;
#pragma unroll
    for (int mi = 0; mi < 2; ++mi) {
        const int o0 = wo * 32 + mi * 16 + r;
        const float bi0 = bias[o0];
        const float bi8 = bias[o0 + 8];
        float* d0 = g_tmp + ((size_t)h * COUT + o0) * B_ + bh * 128 + wb * 64 + cpair;
        float* d8 = d0 + 8 * B_;
#pragma unroll
        for (int ni = 0; ni < 8; ++ni) {
            float2 v0, v8;
            v0.x = acc[mi][ni][0] * sc + bi0;
            v0.y = acc[mi][ni][1] * sc + bi0;
            v8.x = acc[mi][ni][2] * sc + bi8;
            v8.y = acc[mi][ni][3] * sc + bi8;
            *(float2*)(d0 + ni * 8) = v0;
            *(float2*)(d8 + ni * 8) = v8;
        }
    }
}

// ---------------------------------------------------------------------------
// Kernel 4: tmp[h][o][b] -> out[b][o][h]  (tiled transpose per o)
// ---------------------------------------------------------------------------
__global__ void k_transpose_out(float* __restrict__ out) {
    __shared__ float t[32][33];
    const int o  = blockIdx.z;
    const int h0 = blockIdx.x * 32;
    const int b0 = blockIdx.y * 32;
    const int tx = threadIdx.x, ty = threadIdx.y;

#pragma unroll
    for (int i = 0; i < 32; i += 8) {
        int b = b0 + tx;
        int hh = h0 + ty + i;
        if (hh < H_)
            t[ty + i][tx] = g_tmp[((size_t)hh * COUT + o) * B_ + b];
    }
    __syncthreads();
#pragma unroll
    for (int i = 0; i < 32; i += 8) {
        int hh = h0 + tx;
        int b = b0 + ty + i;
        if (hh < H_)
            out[((size_t)b * COUT + o) * H_ + hh] = t[tx][ty + i];
    }
}

// ---------------------------------------------------------------------------
// Launch
// Inputs: x[f32], neighbors[int32], weight_center[f32], weight_neighbors[f32],
//         bias[f32]
// ---------------------------------------------------------------------------
extern "C" void kernel_launch(void* const* d_in, const int* in_sizes, int n_in,
                              void* d_out, int out_size) {
    const float* x    = (const float*)d_in[0];
    const int*   nb   = (const int*)d_in[1];
    const float* wc   = (const float*)d_in[2];
    const float* wn   = (const float*)d_in[3];
    const float* bias = (const float*)d_in[4];
    float* out = (float*)d_out;

    // 1) transpose + fp16 convert of x
    k_prep_x<<<dim3((H_ + 31) / 32, (B_ * CIN) / 32), dim3(32, 8)>>>(x);

    // 2) pack weights into fragment order
    k_pack_w<<<(KT * COUT * CIN + 255) / 256, 256>>>(wc, wn);

    // 3) main HMMA GEMM, 2 CTAs per hexagon (b-halves)
    cudaFuncSetAttribute(k_main, cudaFuncAttributeMaxDynamicSharedMemorySize,
                         DSMEM_BYTES);
    k_main<<<dim3(2, H_), 256, DSMEM_BYTES>>>(nb, bias);

    // 4) transpose tmp -> out
    k_transpose_out<<<dim3((H_ + 31) / 32, B_ / 32, COUT), dim3(32, 8)>>>(out);
}

// round 6
// speedup vs baseline: 4.3135x; 1.0516x over previous
#include <cuda_runtime.h>
#include <cuda_fp16.h>
#include <cstdint>

// Problem constants
#define B_   256
#define CIN  64
#define COUT 128
#define H_   1039
#define KN   6          // max neighbors
#define KT   7          // center + neighbors

// Static device scratch (allocation-guard safe)
__device__ __align__(256) __half g_x[(size_t)H_ * B_ * CIN];    // [h][b][c] fp16
__device__ __align__(256) __half g_wfrag[KT * COUT * CIN];      // fragment-order fp16
__device__ __align__(256) __half g_tmp[(size_t)H_ * COUT * B_]; // [h][o][b] fp16 (post scale+bias)

// ---------------------------------------------------------------------------
// PTX helpers (baseline ISA only — toolchain lowers through compute_103)
// ---------------------------------------------------------------------------
__device__ __forceinline__ uint32_t smem_u32(const void* p) {
    uint32_t r;
    asm("{ .reg .u64 t; cvta.to.shared.u64 t, %1; cvt.u32.u64 %0, t; }"
        : "=r"(r) : "l"(p));
    return r;
}
__device__ __forceinline__ void cpasync16(uint32_t s, const void* g) {
    asm volatile("cp.async.ca.shared.global [%0], [%1], 16;"
                 :: "r"(s), "l"(g) : "memory");
}
#define CP_COMMIT() asm volatile("cp.async.commit_group;" ::: "memory")
#define CP_WAIT(n)  asm volatile("cp.async.wait_group %0;" :: "n"(n) : "memory")

#define LDSM_X4(r, addr) \
    asm volatile("ldmatrix.sync.aligned.m8n8.x4.shared.b16 {%0,%1,%2,%3}, [%4];" \
                 : "=r"((r)[0]), "=r"((r)[1]), "=r"((r)[2]), "=r"((r)[3]) \
                 : "r"(addr))

__device__ __forceinline__ void mma_fp16(float* c, const uint32_t* a,
                                         uint32_t b0, uint32_t b1) {
    asm volatile(
        "mma.sync.aligned.m16n8k16.row.col.f32.f16.f16.f32 "
        "{%0,%1,%2,%3}, {%4,%5,%6,%7}, {%8,%9}, {%0,%1,%2,%3};"
        : "+f"(c[0]), "+f"(c[1]), "+f"(c[2]), "+f"(c[3])
        : "r"(a[0]), "r"(a[1]), "r"(a[2]), "r"(a[3]), "r"(b0), "r"(b1));
}

// ---------------------------------------------------------------------------
// Kernel 1: x[b][c][h] (viewed [m=bc][h]) -> g_x[h][m] fp16
// ---------------------------------------------------------------------------
__global__ void k_prep_x(const float* __restrict__ x) {
    __shared__ float t[32][33];
    const int h0 = blockIdx.x * 32;
    const int m0 = blockIdx.y * 32;
    const int tx = threadIdx.x, ty = threadIdx.y;

#pragma unroll
    for (int i = 0; i < 32; i += 8) {
        int h = h0 + tx;
        if (h < H_)
            t[ty + i][tx] = x[(size_t)(m0 + ty + i) * H_ + h];
    }
    __syncthreads();
#pragma unroll
    for (int i = 0; i < 32; i += 8) {
        int h = h0 + ty + i;
        int m = m0 + tx;
        if (h < H_)
            g_x[(size_t)h * (B_ * CIN) + m] = __float2half(t[tx][ty + i]);
    }
}

// ---------------------------------------------------------------------------
// Kernel 2: pack weights into per-lane MMA fragment order (fp16).
// addr16 = ((k*8 + MI)*4 + ks)*32 + lane; 8 halves per lane-chunk:
//   e = j*2 + hh (j = mma A reg 0..3)
//   row(o) = MI*16 + (j&1)*8 + (lane>>2)
//   col(c) = ks*16 + ((j>>1)&1)*8 + (lane&3)*2 + hh
// ---------------------------------------------------------------------------
__global__ void k_pack_w(const float* __restrict__ wc, const float* __restrict__ wn) {
    int t = blockIdx.x * blockDim.x + threadIdx.x;
    if (t >= KT * COUT * CIN) return;
    int k    = t >> 13;
    int rem  = t & 8191;
    int mi   = rem >> 10;
    int rem2 = rem & 1023;
    int ks   = rem2 >> 8;
    int rem3 = rem2 & 255;
    int ln   = rem3 >> 3;
    int e    = rem3 & 7;
    int j    = e >> 1;
    int hh   = e & 1;
    int o = mi * 16 + (j & 1) * 8 + (ln >> 2);
    int c = ks * 16 + ((j >> 1) & 1) * 8 + (ln & 3) * 2 + hh;
    float v = (k == 0) ? wc[o * CIN + c]
                       : wn[(o * CIN + c) * KN + (k - 1)];
    g_wfrag[t] = __float2half(v);
}

// ---------------------------------------------------------------------------
// Kernel 3: main HMMA GEMM. Grid (2 b-halves, H). CTA tile o=128 x b=128.
// 8 warps, warp tile 32(o) x 64(b). Single fp16 term, fp32 accumulate.
// 16KB B stages, 3-stage cp.async ring, one barrier per chunk, occupancy 2.
// A fragments LDG'd from L1-resident pre-packed weights. fp16 epilogue store.
// ---------------------------------------------------------------------------
#define BT_BYTES 16384                    // 128 rows x 128B
#define NSTAGE 3
#define DSMEM_BYTES (NSTAGE * BT_BYTES + 1024)

extern __shared__ char dsm[];

// swizzled smem offset for (row, 16B-chunk c) within a tile of 128B rows
__device__ __forceinline__ uint32_t swz(uint32_t row, uint32_t c) {
    return row * 128u + ((c ^ (row & 7u)) * 16u);
}

__global__ void __launch_bounds__(256, 2)
k_main(const int* __restrict__ neighbors, const float* __restrict__ bias) {
    __shared__ int s_idx[KT];
    __shared__ int s_n;
    __shared__ float s_scale;

    const int h    = blockIdx.y;
    const int bh   = blockIdx.x;          // b-half: rows bh*128 .. bh*128+127
    const int tid  = threadIdx.x;
    const int wid  = tid >> 5;
    const int lane = tid & 31;
    const int wo   = wid & 3;             // o-quarter (32 rows)
    const int wb   = wid >> 2;            // b 64-half within the 128

    const uint32_t sraw  = smem_u32(dsm);
    const uint32_t sbase = (sraw + 1023u) & ~1023u;

    if (tid == 0) {
        s_idx[0] = h;
        int n = 1;
#pragma unroll
        for (int k = 0; k < KN; ++k) {
            int v = neighbors[h * KN + k];
            if (v >= 0) s_idx[n++] = v;   // valid-prefix: slot i -> weight chunk i
        }
        s_n = n;
        s_scale = 1.0f / (float)n;
    }
    __syncthreads();

    const int n = s_n;
    const size_t boff = (size_t)bh * 128 * CIN;

    // ---- stage loader: chunk ci -> ring buffer j (128 rows of this b-half) ----
    auto load_stage = [&](int ci, int j) {
        const char* Bsrc = (const char*)(g_x + (size_t)s_idx[ci] * (B_ * CIN) + boff);
        const uint32_t sb = sbase + (uint32_t)j * BT_BYTES;
#pragma unroll
        for (int p = 0; p < 4; ++p) {             // 1024 16B chunks
            int id = tid + p * 256;
            uint32_t sw = swz((uint32_t)(id >> 3), (uint32_t)(id & 7));
            cpasync16(sb + sw, Bsrc + (size_t)id * 16);
        }
    };

    float acc[2][8][4];
#pragma unroll
    for (int mi = 0; mi < 2; ++mi)
#pragma unroll
        for (int ni = 0; ni < 8; ++ni)
#pragma unroll
            for (int q = 0; q < 4; ++q) acc[mi][ni][q] = 0.0f;

    load_stage(0, 0); CP_COMMIT();
    load_stage(1, 1); CP_COMMIT();

    const uint32_t b_lr = (uint32_t)((lane & 7) + ((lane & 16) >> 1)); // 0..15
    const uint32_t b_lc = (uint32_t)((lane >> 3) & 1);

    const uint4* __restrict__ wf = (const uint4*)g_wfrag;

    for (int i = 0; i < n; ++i) {
        if (i < n - 1) { CP_WAIT(1); } else { CP_WAIT(0); }
        __syncthreads();

        if (i + 2 < n) { load_stage(i + 2, (i + 2) % NSTAGE); CP_COMMIT(); }

        const uint32_t st = sbase + (uint32_t)(i % NSTAGE) * BT_BYTES;
        const uint4* wfk = wf + (size_t)i * 1024;

#pragma unroll
        for (int ks = 0; ks < 4; ++ks) {
            uint32_t a[2][4];
#pragma unroll
            for (int mi = 0; mi < 2; ++mi) {
                int MI = wo * 2 + mi;                         // o-row group 0..7
                uint4 v = wfk[((MI * 4 + ks) * 32) + lane];
                a[mi][0] = v.x; a[mi][1] = v.y; a[mi][2] = v.z; a[mi][3] = v.w;
            }
            uint32_t b[4][4];
#pragma unroll
            for (int nt = 0; nt < 4; ++nt) {
                uint32_t row = (uint32_t)(wb * 64 + nt * 16) + b_lr;
                LDSM_X4(b[nt], st + swz(row, (uint32_t)(ks * 2) + b_lc));
            }
#pragma unroll
            for (int mi = 0; mi < 2; ++mi)
#pragma unroll
                for (int nt = 0; nt < 4; ++nt) {
                    mma_fp16(acc[mi][2 * nt],     a[mi], b[nt][0], b[nt][1]);
                    mma_fp16(acc[mi][2 * nt + 1], a[mi], b[nt][2], b[nt][3]);
                }
        }
    }

    // ---- epilogue: scale + bias, fp16 store to g_tmp[h][o][b] ----
    const float sc = s_scale;
    const int r     = lane >> 2;
    const int cpair = (lane & 3) * 2;
#pragma unroll
    for (int mi = 0; mi < 2; ++mi) {
        const int o0 = wo * 32 + mi * 16 + r;
        const float bi0 = bias[o0];
        const float bi8 = bias[o0 + 8];
        __half* d0 = g_tmp + ((size_t)h * COUT + o0) * B_ + bh * 128 + wb * 64 + cpair;
        __half* d8 = d0 + 8 * B_;
#pragma unroll
        for (int ni = 0; ni < 8; ++ni) {
            __half2 v0 = __floats2half2_rn(acc[mi][ni][0] * sc + bi0,
                                           acc[mi][ni][1] * sc + bi0);
            __half2 v8 = __floats2half2_rn(acc[mi][ni][2] * sc + bi8,
                                           acc[mi][ni][3] * sc + bi8);
            *(__half2*)(d0 + ni * 8) = v0;
            *(__half2*)(d8 + ni * 8) = v8;
        }
    }
}

// ---------------------------------------------------------------------------
// Kernel 4: tmp[h][o][b] (fp16) -> out[b][o][h] (fp32)  tiled transpose per o
// ---------------------------------------------------------------------------
__global__ void k_transpose_out(float* __restrict__ out) {
    __shared__ float t[32][33];
    const int o  = blockIdx.z;
    const int h0 = blockIdx.x * 32;
    const int b0 = blockIdx.y * 32;
    const int tx = threadIdx.x, ty = threadIdx.y;

#pragma unroll
    for (int i = 0; i < 32; i += 8) {
        int b = b0 + tx;
        int hh = h0 + ty + i;
        if (hh < H_)
            t[ty + i][tx] = __half2float(g_tmp[((size_t)hh * COUT + o) * B_ + b]);
    }
    __syncthreads();
#pragma unroll
    for (int i = 0; i < 32; i += 8) {
        int hh = h0 + tx;
        int b = b0 + ty + i;
        if (hh < H_)
            out[((size_t)b * COUT + o) * H_ + hh] = t[tx][ty + i];
    }
}

// ---------------------------------------------------------------------------
// Launch
// Inputs: x[f32], neighbors[int32], weight_center[f32], weight_neighbors[f32],
//         bias[f32]
// ---------------------------------------------------------------------------
extern "C" void kernel_launch(void* const* d_in, const int* in_sizes, int n_in,
                              void* d_out, int out_size) {
    const float* x    = (const float*)d_in[0];
    const int*   nb   = (const int*)d_in[1];
    const float* wc   = (const float*)d_in[2];
    const float* wn   = (const float*)d_in[3];
    const float* bias = (const float*)d_in[4];
    float* out = (float*)d_out;

    // 1) transpose + fp16 convert of x
    k_prep_x<<<dim3((H_ + 31) / 32, (B_ * CIN) / 32), dim3(32, 8)>>>(x);

    // 2) pack weights into fragment order
    k_pack_w<<<(KT * COUT * CIN + 255) / 256, 256>>>(wc, wn);

    // 3) main HMMA GEMM, 2 CTAs per hexagon (b-halves)
    cudaFuncSetAttribute(k_main, cudaFuncAttributeMaxDynamicSharedMemorySize,
                         DSMEM_BYTES);
    k_main<<<dim3(2, H_), 256, DSMEM_BYTES>>>(nb, bias);

    // 4) transpose tmp -> out
    k_transpose_out<<<dim3((H_ + 31) / 32, B_ / 32, COUT), dim3(32, 8)>>>(out);
}